// round 11
// baseline (speedup 1.0000x reference)
#include <cuda_runtime.h>
#include <cuda_bf16.h>
#include <cstdint>

#define NB 8
#define L  2050
#define D  320
#define KU 640              // unique packed K = 2*D  (hi | lo)
#define MTOT (NB * L)

// ---------------------------------------------------------------------------
// Compact packed bf16 operands (unique data only):
//   xp row = [x_hi(320) | x_lo(320)],  yp row = [y_hi(320) | y_lo(320)]
//   wp row e = [Wh(:,e)(320) | Wl(:,e)(320)]
// Compensated product by fragment reuse: acc += ah*bh + ah*bl + al*bh
// ---------------------------------------------------------------------------
__device__ __align__(1024) __nv_bfloat16 g_xp[MTOT * KU];
__device__ __align__(1024) __nv_bfloat16 g_yp[MTOT * KU];
__device__ __align__(1024) __nv_bfloat16 g_wp[D * KU];

__device__ __forceinline__ uint32_t smem_u32(const void* p) {
    uint32_t a;
    asm("{ .reg .u64 t; cvta.to.shared.u64 t, %1; cvt.u32.u64 %0, t; }" : "=r"(a) : "l"(p));
    return a;
}
__device__ __forceinline__ void cp_async16(uint32_t dst, const void* src) {
    asm volatile("cp.async.cg.shared.global [%0], [%1], 16;" :: "r"(dst), "l"(src) : "memory");
}
__device__ __forceinline__ void cp_commit() {
    asm volatile("cp.async.commit_group;" ::: "memory");
}
template <int N>
__device__ __forceinline__ void cp_wait() {
    asm volatile("cp.async.wait_group %0;" :: "n"(N) : "memory");
}
__device__ __forceinline__ void ldmatrix_x4(uint32_t* r, uint32_t addr) {
    asm volatile("ldmatrix.sync.aligned.m8n8.x4.shared.b16 {%0,%1,%2,%3}, [%4];"
                 : "=r"(r[0]), "=r"(r[1]), "=r"(r[2]), "=r"(r[3]) : "r"(addr));
}
__device__ __forceinline__ void mma16816(float* c, const uint32_t* a, uint32_t b0, uint32_t b1) {
    asm volatile("mma.sync.aligned.m16n8k16.row.col.f32.bf16.bf16.f32 "
                 "{%0,%1,%2,%3}, {%4,%5,%6,%7}, {%8,%9}, {%0,%1,%2,%3};"
                 : "+f"(c[0]), "+f"(c[1]), "+f"(c[2]), "+f"(c[3])
                 : "r"(a[0]), "r"(a[1]), "r"(a[2]), "r"(a[3]), "r"(b0), "r"(b1));
}
__device__ __forceinline__ uint32_t sw128(uint32_t off) {
    return off ^ ((off >> 3) & 0x70);
}
__device__ __forceinline__ uint32_t pack_bf2(__nv_bfloat16 a, __nv_bfloat16 b) {
    return (uint32_t)__bfloat16_as_ushort(a) | ((uint32_t)__bfloat16_as_ushort(b) << 16);
}
// sigmoid(z) = 0.5*tanh(0.5*z) + 0.5, single MUFU
__device__ __forceinline__ float fast_sigmoid_half(float zh) {
    float t;
    asm("tanh.approx.f32 %0, %1;" : "=f"(t) : "f"(zh));
    return fmaf(t, 0.5f, 0.5f);
}

// ---------------------------------------------------------------------------
// Kernel 0 (fused): split x -> xp [hi|lo] (8 elems/thread, uint4 stores)
//                   AND pack W -> wp
// ---------------------------------------------------------------------------
#define NX8 (MTOT * D / 8)
#define NW  (D * D)

__global__ __launch_bounds__(256) void split_pack_kernel(const float* __restrict__ X,
                                                         const float* __restrict__ W)
{
    int gi = blockIdx.x * blockDim.x + threadIdx.x;
    if (gi < NX8) {
        const float4* X4 = reinterpret_cast<const float4*>(X);
        float4 v0 = X4[gi * 2];
        float4 v1 = X4[gi * 2 + 1];
        float vv[8] = {v0.x, v0.y, v0.z, v0.w, v1.x, v1.y, v1.z, v1.w};
        uint32_t hp[4], lp[4];
#pragma unroll
        for (int q = 0; q < 4; q++) {
            __nv_bfloat16 h0 = __float2bfloat16(vv[q * 2]);
            __nv_bfloat16 h1 = __float2bfloat16(vv[q * 2 + 1]);
            __nv_bfloat16 l0 = __float2bfloat16(vv[q * 2]     - __bfloat162float(h0));
            __nv_bfloat16 l1 = __float2bfloat16(vv[q * 2 + 1] - __bfloat162float(h1));
            hp[q] = pack_bf2(h0, h1);
            lp[q] = pack_bf2(l0, l1);
        }
        int row = (gi * 8) / D;
        int col = (gi * 8) % D;        // D % 8 == 0
        __nv_bfloat16* base = g_xp + (size_t)row * KU;
        *reinterpret_cast<uint4*>(base + col)       = make_uint4(hp[0], hp[1], hp[2], hp[3]);
        *reinterpret_cast<uint4*>(base + 320 + col) = make_uint4(lp[0], lp[1], lp[2], lp[3]);
    } else {
        int i = gi - NX8;
        if (i >= NW) return;
        int d = i / D, e = i % D;
        float w = W[(size_t)d * D + e];
        __nv_bfloat16 h = __float2bfloat16(w);
        __nv_bfloat16 l = __float2bfloat16(w - __bfloat162float(h));
        __nv_bfloat16* base = g_wp + (size_t)e * KU;
        base[d]       = h;
        base[320 + d] = l;
    }
}

// ---------------------------------------------------------------------------
// Kernel 1: y = x @ W via compensated bf16 mma (NT: A=xp, B=wp).
// CTA 128x64, 8 warps (4m x 2n), warp 32x32. 3-stage pipe, mid-loop issue.
// (R9 configuration — measured best.)  Epilogue -> yp [hi | lo].
// ---------------------------------------------------------------------------
#define XW_STAGE ((128 + 64) * 128)              // 24576 B
#define XW_NSTAGE 3
#define XW_NKB 10

__global__ __launch_bounds__(256, 2) void xw_mma(void)
{
    extern __shared__ char smem[];
    const uint32_t sbase = smem_u32(smem);
    const int tid  = threadIdx.x;
    const int wid  = tid >> 5;
    const int lane = tid & 31;

    const int row0 = blockIdx.y * 128;
    const int col0 = blockIdx.x * 64;
    const int wm = (wid >> 1) * 32;
    const int wn = (wid & 1) * 32;

    float acc[2][4][4];
#pragma unroll
    for (int mi = 0; mi < 2; mi++)
#pragma unroll
        for (int ni = 0; ni < 4; ni++)
#pragma unroll
            for (int e = 0; e < 4; e++) acc[mi][ni][e] = 0.0f;

    auto load_tiles = [&](int kb) {
        if (kb >= XW_NKB) return;
        const uint32_t stage = sbase + (uint32_t)(kb % XW_NSTAGE) * XW_STAGE;
        const int koff = kb * 32;
#pragma unroll
        for (int it = tid; it < 1024; it += 256) {
            int r = it >> 3, c = it & 7;
            int scol = koff + (c & 3) * 8 + ((c >> 2) * 320);
            uint32_t dst = stage + sw128((uint32_t)(r * 128 + c * 16));
            int grow = row0 + r;
            if (grow < MTOT) cp_async16(dst, g_xp + (size_t)grow * KU + scol);
            else *reinterpret_cast<uint4*>(smem + (dst - sbase)) = make_uint4(0, 0, 0, 0);
        }
#pragma unroll
        for (int it = tid; it < 512; it += 256) {
            int r = it >> 3, c = it & 7;
            int scol = koff + (c & 3) * 8 + ((c >> 2) * 320);
            uint32_t dst = stage + 16384 + sw128((uint32_t)(r * 128 + c * 16));
            cp_async16(dst, g_wp + (size_t)(col0 + r) * KU + scol);
        }
    };

    load_tiles(0); cp_commit();
    load_tiles(1); cp_commit();

    for (int kb = 0; kb < XW_NKB; kb++) {
        cp_wait<1>();
        __syncthreads();

        const uint32_t sA = sbase + (uint32_t)(kb % XW_NSTAGE) * XW_STAGE;
        const uint32_t sB = sA + 16384;

#pragma unroll
        for (int ks = 0; ks < 2; ks++) {
            uint32_t a[2][4], bh[2][4], bl[2][4];
            const int ca = ks * 2 + (lane >> 4);
            const int cb = ks * 2 + ((lane >> 3) & 1);
#pragma unroll
            for (int mi = 0; mi < 2; mi++) {
                int r = wm + mi * 16 + (lane & 7) + ((lane >> 3) & 1) * 8;
                ldmatrix_x4(a[mi], sA + sw128((uint32_t)(r * 128 + ca * 16)));
            }
#pragma unroll
            for (int nj = 0; nj < 2; nj++) {
                int n = wn + nj * 16 + (lane & 7) + (lane >> 4) * 8;
                ldmatrix_x4(bh[nj], sB + sw128((uint32_t)(n * 128 + cb * 16)));
                ldmatrix_x4(bl[nj], sB + sw128((uint32_t)(n * 128 + (cb + 4) * 16)));
            }
#pragma unroll
            for (int nj = 0; nj < 2; nj++)
#pragma unroll
                for (int mi = 0; mi < 2; mi++) {
                    mma16816(acc[mi][nj * 2],     a[mi], bh[nj][0], bh[nj][1]);
                    mma16816(acc[mi][nj * 2 + 1], a[mi], bh[nj][2], bh[nj][3]);
                    mma16816(acc[mi][nj * 2],     a[mi], bl[nj][0], bl[nj][1]);
                    mma16816(acc[mi][nj * 2 + 1], a[mi], bl[nj][2], bl[nj][3]);
                }
#pragma unroll
            for (int mi = 0; mi < 2; mi++) {
                int r = wm + mi * 16 + (lane & 7) + ((lane >> 3) & 1) * 8;
                ldmatrix_x4(a[mi], sA + sw128((uint32_t)(r * 128 + (ca + 4) * 16)));
            }
#pragma unroll
            for (int nj = 0; nj < 2; nj++)
#pragma unroll
                for (int mi = 0; mi < 2; mi++) {
                    mma16816(acc[mi][nj * 2],     a[mi], bh[nj][0], bh[nj][1]);
                    mma16816(acc[mi][nj * 2 + 1], a[mi], bh[nj][2], bh[nj][3]);
                }
            if (ks == 0) { load_tiles(kb + 2); cp_commit(); }
        }
    }

#pragma unroll
    for (int mi = 0; mi < 2; mi++) {
        int r0 = row0 + wm + mi * 16 + (lane >> 2);
#pragma unroll
        for (int ni = 0; ni < 4; ni++) {
            int col = col0 + wn + ni * 8 + (lane & 3) * 2;
#pragma unroll
            for (int h = 0; h < 2; h++) {
                int row = r0 + h * 8;
                if (row >= MTOT) continue;
                float v0 = acc[mi][ni][h * 2];
                float v1 = acc[mi][ni][h * 2 + 1];
                __nv_bfloat16 h0 = __float2bfloat16(v0);
                __nv_bfloat16 h1 = __float2bfloat16(v1);
                __nv_bfloat16 l0 = __float2bfloat16(v0 - __bfloat162float(h0));
                __nv_bfloat16 l1 = __float2bfloat16(v1 - __bfloat162float(h1));
                __nv_bfloat16* base = g_yp + (size_t)row * KU;
                *reinterpret_cast<uint32_t*>(base + col)       = pack_bf2(h0, h1);
                *reinterpret_cast<uint32_t*>(base + 320 + col) = pack_bf2(l0, l1);
            }
        }
    }
}

// ---------------------------------------------------------------------------
// Kernel 2: out = sigmoid(yp · xp^T + bias).  Unique K=640, 10 kb of 32.
// CTA 128x128, 8 warps (2m x 4n), warp 64x32, 2 CTAs/SM, 3-stage pipe.
// Mid-kb prefetch split into TWO half-bursts (A after ks0's first mma block,
// B at end of ks0) so LSU bursts are absorbed by surrounding mma issue.
// ---------------------------------------------------------------------------
#define BL_STAGE ((128 + 128) * 128)             // 32768 B per stage
#define BL_NSTAGE 3
#define BL_NKB 10

__global__ __launch_bounds__(256, 2) void bilinear_mma(const float* __restrict__ bias,
                                                       float* __restrict__ out)
{
    extern __shared__ char smem[];
    const uint32_t sbase = smem_u32(smem);
    const int tid  = threadIdx.x;
    const int wid  = tid >> 5;
    const int lane = tid & 31;

    const int b    = blockIdx.z;
    const int row0 = blockIdx.y * 128;
    const int col0 = blockIdx.x * 128;

    const __nv_bfloat16* Ag = g_yp + (size_t)b * L * KU;
    const __nv_bfloat16* Bg = g_xp + (size_t)b * L * KU;

    const int wm = (wid >> 2) * 64;
    const int wn = (wid & 3) * 32;

    float acc[4][4][4];
#pragma unroll
    for (int mi = 0; mi < 4; mi++)
#pragma unroll
        for (int ni = 0; ni < 4; ni++)
#pragma unroll
            for (int e = 0; e < 4; e++) acc[mi][ni][e] = 0.0f;

    // half = 0: A tile loads; half = 1: B tile loads
    auto load_half = [&](int kb, int half) {
        if (kb >= BL_NKB) return;
        const uint32_t stage = sbase + (uint32_t)(kb % BL_NSTAGE) * BL_STAGE
                             + (half ? 16384u : 0u);
        const int koff = kb * 32;
        const __nv_bfloat16* src = half ? Bg : Ag;
        const int r0 = half ? col0 : row0;
#pragma unroll
        for (int it = tid; it < 1024; it += 256) {
            int r = it >> 3, c = it & 7;
            int scol = koff + (c & 3) * 8 + ((c >> 2) * 320);
            uint32_t dst = stage + sw128((uint32_t)(r * 128 + c * 16));
            int grow = r0 + r;
            if (grow < L) cp_async16(dst, src + (size_t)grow * KU + scol);
            else *reinterpret_cast<uint4*>(smem + (dst - sbase)) = make_uint4(0, 0, 0, 0);
        }
    };

    load_half(0, 0); load_half(0, 1); cp_commit();
    load_half(1, 0); load_half(1, 1); cp_commit();

    for (int kb = 0; kb < BL_NKB; kb++) {
        cp_wait<1>();
        __syncthreads();

        const uint32_t sA = sbase + (uint32_t)(kb % BL_NSTAGE) * BL_STAGE;
        const uint32_t sB = sA + 16384;

#pragma unroll
        for (int ks = 0; ks < 2; ks++) {
            uint32_t a[4][4], bh[2][4], bl[2][4];
            const int ca = ks * 2 + (lane >> 4);
            const int cb = ks * 2 + ((lane >> 3) & 1);
#pragma unroll
            for (int mi = 0; mi < 4; mi++) {
                int r = wm + mi * 16 + (lane & 7) + ((lane >> 3) & 1) * 8;
                ldmatrix_x4(a[mi], sA + sw128((uint32_t)(r * 128 + ca * 16)));
            }
#pragma unroll
            for (int nj = 0; nj < 2; nj++) {
                int n = wn + nj * 16 + (lane & 7) + (lane >> 4) * 8;
                ldmatrix_x4(bh[nj], sB + sw128((uint32_t)(n * 128 + cb * 16)));
                ldmatrix_x4(bl[nj], sB + sw128((uint32_t)(n * 128 + (cb + 4) * 16)));
            }
#pragma unroll
            for (int nj = 0; nj < 2; nj++)
#pragma unroll
                for (int mi = 0; mi < 4; mi++) {
                    mma16816(acc[mi][nj * 2],     a[mi], bh[nj][0], bh[nj][1]);
                    mma16816(acc[mi][nj * 2 + 1], a[mi], bh[nj][2], bh[nj][3]);
                    mma16816(acc[mi][nj * 2],     a[mi], bl[nj][0], bl[nj][1]);
                    mma16816(acc[mi][nj * 2 + 1], a[mi], bl[nj][2], bl[nj][3]);
                }
            // First half-burst: A loads for kb+2, absorbed between mma groups
            if (ks == 0) load_half(kb + 2, 0);
#pragma unroll
            for (int mi = 0; mi < 4; mi++) {
                int r = wm + mi * 16 + (lane & 7) + ((lane >> 3) & 1) * 8;
                ldmatrix_x4(a[mi], sA + sw128((uint32_t)(r * 128 + (ca + 4) * 16)));
            }
#pragma unroll
            for (int nj = 0; nj < 2; nj++)
#pragma unroll
                for (int mi = 0; mi < 4; mi++) {
                    mma16816(acc[mi][nj * 2],     a[mi], bh[nj][0], bh[nj][1]);
                    mma16816(acc[mi][nj * 2 + 1], a[mi], bh[nj][2], bh[nj][3]);
                }
            // Second half-burst: B loads for kb+2, then commit the group
            if (ks == 0) { load_half(kb + 2, 1); cp_commit(); }
        }
    }

    // Epilogue: sigmoid(z) = 0.5*tanh(0.5*(z+bias)) + 0.5
    const float hb = 0.5f * bias[0];
    float* obase = out + (size_t)b * L * L;
#pragma unroll
    for (int mi = 0; mi < 4; mi++) {
        int r0 = row0 + wm + mi * 16 + (lane >> 2);
#pragma unroll
        for (int ni = 0; ni < 4; ni++) {
            int col = col0 + wn + ni * 8 + (lane & 3) * 2;
            if (col >= L) continue;
#pragma unroll
            for (int h = 0; h < 2; h++) {
                int row = r0 + h * 8;
                if (row >= L) continue;
                float zh0 = fmaf(acc[mi][ni][h * 2],     0.5f, hb);
                float zh1 = fmaf(acc[mi][ni][h * 2 + 1], 0.5f, hb);
                float2 o;
                o.x = fast_sigmoid_half(zh0);
                o.y = fast_sigmoid_half(zh1);
                *reinterpret_cast<float2*>(&obase[(size_t)row * L + col]) = o;
            }
        }
    }
}

// ---------------------------------------------------------------------------
extern "C" void kernel_launch(void* const* d_in, const int* in_sizes, int n_in,
                              void* d_out, int out_size)
{
    const float* x    = (const float*)d_in[0];   // (8, 2050, 320)
    const float* W    = (const float*)d_in[1];   // (320, 320)
    const float* bias = (const float*)d_in[2];   // (1,)
    float* out = (float*)d_out;                  // (8, 2050, 2050)

    cudaFuncSetAttribute(xw_mma, cudaFuncAttributeMaxDynamicSharedMemorySize,
                         XW_NSTAGE * XW_STAGE);
    cudaFuncSetAttribute(bilinear_mma, cudaFuncAttributeMaxDynamicSharedMemorySize,
                         BL_NSTAGE * BL_STAGE);

    {
        int ntot = NX8 + NW;
        split_pack_kernel<<<(ntot + 255) / 256, 256>>>(x, W);
    }
    {
        dim3 grid(D / 64, (MTOT + 127) / 128);            // (5, 129)
        xw_mma<<<grid, 256, XW_NSTAGE * XW_STAGE>>>();
    }
    {
        dim3 grid((L + 127) / 128, (L + 127) / 128, NB);  // (17,17,8)
        bilinear_mma<<<grid, 256, BL_NSTAGE * BL_STAGE>>>(bias, out);
    }
}

// round 13
// speedup vs baseline: 1.0428x; 1.0428x over previous
#include <cuda_runtime.h>
#include <cuda_bf16.h>
#include <cstdint>

#define NB 8
#define L  2050
#define D  320
#define KU 640              // unique packed K = 2*D  (hi | lo)
#define MTOT (NB * L)

// ---------------------------------------------------------------------------
// Compact packed bf16 operands (unique data only):
//   xp row = [x_hi(320) | x_lo(320)],  yp row = [y_hi(320) | y_lo(320)]
//   wp row e = [Wh(:,e)(320) | Wl(:,e)(320)]
// Compensated product by fragment reuse: acc += ah*bh + ah*bl + al*bh
// ---------------------------------------------------------------------------
__device__ __align__(1024) __nv_bfloat16 g_xp[MTOT * KU];
__device__ __align__(1024) __nv_bfloat16 g_yp[MTOT * KU];
__device__ __align__(1024) __nv_bfloat16 g_wp[D * KU];

__device__ __forceinline__ uint32_t smem_u32(const void* p) {
    uint32_t a;
    asm("{ .reg .u64 t; cvta.to.shared.u64 t, %1; cvt.u32.u64 %0, t; }" : "=r"(a) : "l"(p));
    return a;
}
__device__ __forceinline__ void cp_async16(uint32_t dst, const void* src) {
    asm volatile("cp.async.cg.shared.global [%0], [%1], 16;" :: "r"(dst), "l"(src) : "memory");
}
__device__ __forceinline__ void cp_commit() {
    asm volatile("cp.async.commit_group;" ::: "memory");
}
template <int N>
__device__ __forceinline__ void cp_wait() {
    asm volatile("cp.async.wait_group %0;" :: "n"(N) : "memory");
}
__device__ __forceinline__ void ldmatrix_x4(uint32_t* r, uint32_t addr) {
    asm volatile("ldmatrix.sync.aligned.m8n8.x4.shared.b16 {%0,%1,%2,%3}, [%4];"
                 : "=r"(r[0]), "=r"(r[1]), "=r"(r[2]), "=r"(r[3]) : "r"(addr));
}
__device__ __forceinline__ void mma16816(float* c, const uint32_t* a, uint32_t b0, uint32_t b1) {
    asm volatile("mma.sync.aligned.m16n8k16.row.col.f32.bf16.bf16.f32 "
                 "{%0,%1,%2,%3}, {%4,%5,%6,%7}, {%8,%9}, {%0,%1,%2,%3};"
                 : "+f"(c[0]), "+f"(c[1]), "+f"(c[2]), "+f"(c[3])
                 : "r"(a[0]), "r"(a[1]), "r"(a[2]), "r"(a[3]), "r"(b0), "r"(b1));
}
__device__ __forceinline__ uint32_t sw128(uint32_t off) {
    return off ^ ((off >> 3) & 0x70);
}
__device__ __forceinline__ uint32_t pack_bf2(__nv_bfloat16 a, __nv_bfloat16 b) {
    return (uint32_t)__bfloat16_as_ushort(a) | ((uint32_t)__bfloat16_as_ushort(b) << 16);
}
// sigmoid(z) = 0.5*tanh(0.5*z) + 0.5, single MUFU
__device__ __forceinline__ float fast_sigmoid_half(float zh) {
    float t;
    asm("tanh.approx.f32 %0, %1;" : "=f"(t) : "f"(zh));
    return fmaf(t, 0.5f, 0.5f);
}
// Streaming (evict-first) 8B store: output is never re-read; keep operands in L2.
__device__ __forceinline__ void stg_cs_f2(float* p, float x, float y) {
    asm volatile("st.global.cs.v2.f32 [%0], {%1, %2};" :: "l"(p), "f"(x), "f"(y) : "memory");
}

// ---------------------------------------------------------------------------
// Kernel 0 (fused): split x -> xp [hi|lo] (8 elems/thread, uint4 stores)
//                   AND pack W -> wp
// ---------------------------------------------------------------------------
#define NX8 (MTOT * D / 8)
#define NW  (D * D)

__global__ __launch_bounds__(256) void split_pack_kernel(const float* __restrict__ X,
                                                         const float* __restrict__ W)
{
    int gi = blockIdx.x * blockDim.x + threadIdx.x;
    if (gi < NX8) {
        const float4* X4 = reinterpret_cast<const float4*>(X);
        float4 v0 = X4[gi * 2];
        float4 v1 = X4[gi * 2 + 1];
        float vv[8] = {v0.x, v0.y, v0.z, v0.w, v1.x, v1.y, v1.z, v1.w};
        uint32_t hp[4], lp[4];
#pragma unroll
        for (int q = 0; q < 4; q++) {
            __nv_bfloat16 h0 = __float2bfloat16(vv[q * 2]);
            __nv_bfloat16 h1 = __float2bfloat16(vv[q * 2 + 1]);
            __nv_bfloat16 l0 = __float2bfloat16(vv[q * 2]     - __bfloat162float(h0));
            __nv_bfloat16 l1 = __float2bfloat16(vv[q * 2 + 1] - __bfloat162float(h1));
            hp[q] = pack_bf2(h0, h1);
            lp[q] = pack_bf2(l0, l1);
        }
        int row = (gi * 8) / D;
        int col = (gi * 8) % D;        // D % 8 == 0
        __nv_bfloat16* base = g_xp + (size_t)row * KU;
        *reinterpret_cast<uint4*>(base + col)       = make_uint4(hp[0], hp[1], hp[2], hp[3]);
        *reinterpret_cast<uint4*>(base + 320 + col) = make_uint4(lp[0], lp[1], lp[2], lp[3]);
    } else {
        int i = gi - NX8;
        if (i >= NW) return;
        int d = i / D, e = i % D;
        float w = W[(size_t)d * D + e];
        __nv_bfloat16 h = __float2bfloat16(w);
        __nv_bfloat16 l = __float2bfloat16(w - __bfloat162float(h));
        __nv_bfloat16* base = g_wp + (size_t)e * KU;
        base[d]       = h;
        base[320 + d] = l;
    }
}

// ---------------------------------------------------------------------------
// Kernel 1: y = x @ W via compensated bf16 mma (NT: A=xp, B=wp).
// CTA 128x64, 8 warps (4m x 2n), warp 32x32. 3-stage pipe, mid-loop issue.
// (Exact R9 configuration — measured best.)  Epilogue -> yp [hi | lo].
// ---------------------------------------------------------------------------
#define XW_STAGE ((128 + 64) * 128)              // 24576 B
#define XW_NSTAGE 3
#define XW_NKB 10

__global__ __launch_bounds__(256, 2) void xw_mma(void)
{
    extern __shared__ char smem[];
    const uint32_t sbase = smem_u32(smem);
    const int tid  = threadIdx.x;
    const int wid  = tid >> 5;
    const int lane = tid & 31;

    const int row0 = blockIdx.y * 128;
    const int col0 = blockIdx.x * 64;
    const int wm = (wid >> 1) * 32;
    const int wn = (wid & 1) * 32;

    float acc[2][4][4];
#pragma unroll
    for (int mi = 0; mi < 2; mi++)
#pragma unroll
        for (int ni = 0; ni < 4; ni++)
#pragma unroll
            for (int e = 0; e < 4; e++) acc[mi][ni][e] = 0.0f;

    auto load_tiles = [&](int kb) {
        if (kb >= XW_NKB) return;
        const uint32_t stage = sbase + (uint32_t)(kb % XW_NSTAGE) * XW_STAGE;
        const int koff = kb * 32;
#pragma unroll
        for (int it = tid; it < 1024; it += 256) {
            int r = it >> 3, c = it & 7;
            int scol = koff + (c & 3) * 8 + ((c >> 2) * 320);
            uint32_t dst = stage + sw128((uint32_t)(r * 128 + c * 16));
            int grow = row0 + r;
            if (grow < MTOT) cp_async16(dst, g_xp + (size_t)grow * KU + scol);
            else *reinterpret_cast<uint4*>(smem + (dst - sbase)) = make_uint4(0, 0, 0, 0);
        }
#pragma unroll
        for (int it = tid; it < 512; it += 256) {
            int r = it >> 3, c = it & 7;
            int scol = koff + (c & 3) * 8 + ((c >> 2) * 320);
            uint32_t dst = stage + 16384 + sw128((uint32_t)(r * 128 + c * 16));
            cp_async16(dst, g_wp + (size_t)(col0 + r) * KU + scol);
        }
    };

    load_tiles(0); cp_commit();
    load_tiles(1); cp_commit();

    for (int kb = 0; kb < XW_NKB; kb++) {
        cp_wait<1>();
        __syncthreads();

        const uint32_t sA = sbase + (uint32_t)(kb % XW_NSTAGE) * XW_STAGE;
        const uint32_t sB = sA + 16384;

#pragma unroll
        for (int ks = 0; ks < 2; ks++) {
            uint32_t a[2][4], bh[2][4], bl[2][4];
            const int ca = ks * 2 + (lane >> 4);
            const int cb = ks * 2 + ((lane >> 3) & 1);
#pragma unroll
            for (int mi = 0; mi < 2; mi++) {
                int r = wm + mi * 16 + (lane & 7) + ((lane >> 3) & 1) * 8;
                ldmatrix_x4(a[mi], sA + sw128((uint32_t)(r * 128 + ca * 16)));
            }
#pragma unroll
            for (int nj = 0; nj < 2; nj++) {
                int n = wn + nj * 16 + (lane & 7) + (lane >> 4) * 8;
                ldmatrix_x4(bh[nj], sB + sw128((uint32_t)(n * 128 + cb * 16)));
                ldmatrix_x4(bl[nj], sB + sw128((uint32_t)(n * 128 + (cb + 4) * 16)));
            }
#pragma unroll
            for (int nj = 0; nj < 2; nj++)
#pragma unroll
                for (int mi = 0; mi < 2; mi++) {
                    mma16816(acc[mi][nj * 2],     a[mi], bh[nj][0], bh[nj][1]);
                    mma16816(acc[mi][nj * 2 + 1], a[mi], bh[nj][2], bh[nj][3]);
                    mma16816(acc[mi][nj * 2],     a[mi], bl[nj][0], bl[nj][1]);
                    mma16816(acc[mi][nj * 2 + 1], a[mi], bl[nj][2], bl[nj][3]);
                }
#pragma unroll
            for (int mi = 0; mi < 2; mi++) {
                int r = wm + mi * 16 + (lane & 7) + ((lane >> 3) & 1) * 8;
                ldmatrix_x4(a[mi], sA + sw128((uint32_t)(r * 128 + (ca + 4) * 16)));
            }
#pragma unroll
            for (int nj = 0; nj < 2; nj++)
#pragma unroll
                for (int mi = 0; mi < 2; mi++) {
                    mma16816(acc[mi][nj * 2],     a[mi], bh[nj][0], bh[nj][1]);
                    mma16816(acc[mi][nj * 2 + 1], a[mi], bh[nj][2], bh[nj][3]);
                }
            if (ks == 0) { load_tiles(kb + 2); cp_commit(); }
        }
    }

#pragma unroll
    for (int mi = 0; mi < 2; mi++) {
        int r0 = row0 + wm + mi * 16 + (lane >> 2);
#pragma unroll
        for (int ni = 0; ni < 4; ni++) {
            int col = col0 + wn + ni * 8 + (lane & 3) * 2;
#pragma unroll
            for (int h = 0; h < 2; h++) {
                int row = r0 + h * 8;
                if (row >= MTOT) continue;
                float v0 = acc[mi][ni][h * 2];
                float v1 = acc[mi][ni][h * 2 + 1];
                __nv_bfloat16 h0 = __float2bfloat16(v0);
                __nv_bfloat16 h1 = __float2bfloat16(v1);
                __nv_bfloat16 l0 = __float2bfloat16(v0 - __bfloat162float(h0));
                __nv_bfloat16 l1 = __float2bfloat16(v1 - __bfloat162float(h1));
                __nv_bfloat16* base = g_yp + (size_t)row * KU;
                *reinterpret_cast<uint32_t*>(base + col)       = pack_bf2(h0, h1);
                *reinterpret_cast<uint32_t*>(base + 320 + col) = pack_bf2(l0, l1);
            }
        }
    }
}

// ---------------------------------------------------------------------------
// Kernel 2: out = sigmoid(yp · xp^T + bias).  Unique K=640, 10 kb of 32.
// CTA 128x128, 8 warps (2m x 4n), warp 64x32, 2 CTAs/SM, 3-stage pipe,
// single mid-kb prefetch issue (exact R9). Epilogue stores use st.global.cs
// (streaming) so the 134MB output doesn't evict xp/yp from L2.
// ---------------------------------------------------------------------------
#define BL_STAGE ((128 + 128) * 128)             // 32768 B per stage
#define BL_NSTAGE 3
#define BL_NKB 10

__global__ __launch_bounds__(256, 2) void bilinear_mma(const float* __restrict__ bias,
                                                       float* __restrict__ out)
{
    extern __shared__ char smem[];
    const uint32_t sbase = smem_u32(smem);
    const int tid  = threadIdx.x;
    const int wid  = tid >> 5;
    const int lane = tid & 31;

    const int b    = blockIdx.z;
    const int row0 = blockIdx.y * 128;
    const int col0 = blockIdx.x * 128;

    const __nv_bfloat16* Ag = g_yp + (size_t)b * L * KU;
    const __nv_bfloat16* Bg = g_xp + (size_t)b * L * KU;

    const int wm = (wid >> 2) * 64;
    const int wn = (wid & 3) * 32;

    float acc[4][4][4];
#pragma unroll
    for (int mi = 0; mi < 4; mi++)
#pragma unroll
        for (int ni = 0; ni < 4; ni++)
#pragma unroll
            for (int e = 0; e < 4; e++) acc[mi][ni][e] = 0.0f;

    auto load_tiles = [&](int kb) {
        if (kb >= BL_NKB) return;
        const uint32_t stage = sbase + (uint32_t)(kb % BL_NSTAGE) * BL_STAGE;
        const int koff = kb * 32;
#pragma unroll
        for (int it = tid; it < 1024; it += 256) {
            int r = it >> 3, c = it & 7;
            int scol = koff + (c & 3) * 8 + ((c >> 2) * 320);
            uint32_t dst = stage + sw128((uint32_t)(r * 128 + c * 16));
            int grow = row0 + r;
            if (grow < L) cp_async16(dst, Ag + (size_t)grow * KU + scol);
            else *reinterpret_cast<uint4*>(smem + (dst - sbase)) = make_uint4(0, 0, 0, 0);
        }
#pragma unroll
        for (int it = tid; it < 1024; it += 256) {
            int r = it >> 3, c = it & 7;
            int scol = koff + (c & 3) * 8 + ((c >> 2) * 320);
            uint32_t dst = stage + 16384 + sw128((uint32_t)(r * 128 + c * 16));
            int grow = col0 + r;
            if (grow < L) cp_async16(dst, Bg + (size_t)grow * KU + scol);
            else *reinterpret_cast<uint4*>(smem + (dst - sbase)) = make_uint4(0, 0, 0, 0);
        }
    };

    load_tiles(0); cp_commit();
    load_tiles(1); cp_commit();

    for (int kb = 0; kb < BL_NKB; kb++) {
        cp_wait<1>();
        __syncthreads();

        const uint32_t sA = sbase + (uint32_t)(kb % BL_NSTAGE) * BL_STAGE;
        const uint32_t sB = sA + 16384;

#pragma unroll
        for (int ks = 0; ks < 2; ks++) {
            uint32_t a[4][4], bh[2][4], bl[2][4];
            const int ca = ks * 2 + (lane >> 4);
            const int cb = ks * 2 + ((lane >> 3) & 1);
#pragma unroll
            for (int mi = 0; mi < 4; mi++) {
                int r = wm + mi * 16 + (lane & 7) + ((lane >> 3) & 1) * 8;
                ldmatrix_x4(a[mi], sA + sw128((uint32_t)(r * 128 + ca * 16)));
            }
#pragma unroll
            for (int nj = 0; nj < 2; nj++) {
                int n = wn + nj * 16 + (lane & 7) + (lane >> 4) * 8;
                ldmatrix_x4(bh[nj], sB + sw128((uint32_t)(n * 128 + cb * 16)));
                ldmatrix_x4(bl[nj], sB + sw128((uint32_t)(n * 128 + (cb + 4) * 16)));
            }
#pragma unroll
            for (int nj = 0; nj < 2; nj++)
#pragma unroll
                for (int mi = 0; mi < 4; mi++) {
                    mma16816(acc[mi][nj * 2],     a[mi], bh[nj][0], bh[nj][1]);
                    mma16816(acc[mi][nj * 2 + 1], a[mi], bh[nj][2], bh[nj][3]);
                    mma16816(acc[mi][nj * 2],     a[mi], bl[nj][0], bl[nj][1]);
                    mma16816(acc[mi][nj * 2 + 1], a[mi], bl[nj][2], bl[nj][3]);
                }
#pragma unroll
            for (int mi = 0; mi < 4; mi++) {
                int r = wm + mi * 16 + (lane & 7) + ((lane >> 3) & 1) * 8;
                ldmatrix_x4(a[mi], sA + sw128((uint32_t)(r * 128 + (ca + 4) * 16)));
            }
#pragma unroll
            for (int nj = 0; nj < 2; nj++)
#pragma unroll
                for (int mi = 0; mi < 4; mi++) {
                    mma16816(acc[mi][nj * 2],     a[mi], bh[nj][0], bh[nj][1]);
                    mma16816(acc[mi][nj * 2 + 1], a[mi], bh[nj][2], bh[nj][3]);
                }
            if (ks == 0) { load_tiles(kb + 2); cp_commit(); }
        }
    }

    // Epilogue: sigmoid(z) = 0.5*tanh(0.5*(z+bias)) + 0.5, streaming stores.
    const float hb = 0.5f * bias[0];
    float* obase = out + (size_t)b * L * L;
#pragma unroll
    for (int mi = 0; mi < 4; mi++) {
        int r0 = row0 + wm + mi * 16 + (lane >> 2);
#pragma unroll
        for (int ni = 0; ni < 4; ni++) {
            int col = col0 + wn + ni * 8 + (lane & 3) * 2;
            if (col >= L) continue;
#pragma unroll
            for (int h = 0; h < 2; h++) {
                int row = r0 + h * 8;
                if (row >= L) continue;
                float zh0 = fmaf(acc[mi][ni][h * 2],     0.5f, hb);
                float zh1 = fmaf(acc[mi][ni][h * 2 + 1], 0.5f, hb);
                stg_cs_f2(&obase[(size_t)row * L + col],
                          fast_sigmoid_half(zh0), fast_sigmoid_half(zh1));
            }
        }
    }
}

// ---------------------------------------------------------------------------
extern "C" void kernel_launch(void* const* d_in, const int* in_sizes, int n_in,
                              void* d_out, int out_size)
{
    const float* x    = (const float*)d_in[0];   // (8, 2050, 320)
    const float* W    = (const float*)d_in[1];   // (320, 320)
    const float* bias = (const float*)d_in[2];   // (1,)
    float* out = (float*)d_out;                  // (8, 2050, 2050)

    cudaFuncSetAttribute(xw_mma, cudaFuncAttributeMaxDynamicSharedMemorySize,
                         XW_NSTAGE * XW_STAGE);
    cudaFuncSetAttribute(bilinear_mma, cudaFuncAttributeMaxDynamicSharedMemorySize,
                         BL_NSTAGE * BL_STAGE);

    {
        int ntot = NX8 + NW;
        split_pack_kernel<<<(ntot + 255) / 256, 256>>>(x, W);
    }
    {
        dim3 grid(D / 64, (MTOT + 127) / 128);            // (5, 129)
        xw_mma<<<grid, 256, XW_NSTAGE * XW_STAGE>>>();
    }
    {
        dim3 grid((L + 127) / 128, (L + 127) / 128, NB);  // (17,17,8)
        bilinear_mma<<<grid, 256, BL_NSTAGE * BL_STAGE>>>(bias, out);
    }
}

// round 14
// speedup vs baseline: 1.0723x; 1.0284x over previous
#include <cuda_runtime.h>
#include <cuda_bf16.h>
#include <cstdint>

#define NB 8
#define L  2050
#define D  320
#define KU 640              // unique packed K = 2*D  (hi | lo)
#define MTOT (NB * L)

// ---------------------------------------------------------------------------
// Compact packed bf16 operands (unique data only):
//   xp row = [x_hi(320) | x_lo(320)],  yp row = [y_hi(320) | y_lo(320)]
//   wp row e = [Wh(:,e)(320) | Wl(:,e)(320)]
// Compensated product by fragment reuse: acc += ah*bh + ah*bl + al*bh
// ---------------------------------------------------------------------------
__device__ __align__(1024) __nv_bfloat16 g_xp[MTOT * KU];
__device__ __align__(1024) __nv_bfloat16 g_yp[MTOT * KU];
__device__ __align__(1024) __nv_bfloat16 g_wp[D * KU];

__device__ __forceinline__ uint32_t smem_u32(const void* p) {
    uint32_t a;
    asm("{ .reg .u64 t; cvta.to.shared.u64 t, %1; cvt.u32.u64 %0, t; }" : "=r"(a) : "l"(p));
    return a;
}
__device__ __forceinline__ void cp_async16(uint32_t dst, const void* src) {
    asm volatile("cp.async.cg.shared.global [%0], [%1], 16;" :: "r"(dst), "l"(src) : "memory");
}
__device__ __forceinline__ void cp_commit() {
    asm volatile("cp.async.commit_group;" ::: "memory");
}
template <int N>
__device__ __forceinline__ void cp_wait() {
    asm volatile("cp.async.wait_group %0;" :: "n"(N) : "memory");
}
__device__ __forceinline__ void ldmatrix_x4(uint32_t* r, uint32_t addr) {
    asm volatile("ldmatrix.sync.aligned.m8n8.x4.shared.b16 {%0,%1,%2,%3}, [%4];"
                 : "=r"(r[0]), "=r"(r[1]), "=r"(r[2]), "=r"(r[3]) : "r"(addr));
}
__device__ __forceinline__ void mma16816(float* c, const uint32_t* a, uint32_t b0, uint32_t b1) {
    asm volatile("mma.sync.aligned.m16n8k16.row.col.f32.bf16.bf16.f32 "
                 "{%0,%1,%2,%3}, {%4,%5,%6,%7}, {%8,%9}, {%0,%1,%2,%3};"
                 : "+f"(c[0]), "+f"(c[1]), "+f"(c[2]), "+f"(c[3])
                 : "r"(a[0]), "r"(a[1]), "r"(a[2]), "r"(a[3]), "r"(b0), "r"(b1));
}
__device__ __forceinline__ uint32_t sw128(uint32_t off) {
    return off ^ ((off >> 3) & 0x70);
}
__device__ __forceinline__ uint32_t pack_bf2(__nv_bfloat16 a, __nv_bfloat16 b) {
    return (uint32_t)__bfloat16_as_ushort(a) | ((uint32_t)__bfloat16_as_ushort(b) << 16);
}
// sigmoid(z) = 0.5*tanh(0.5*z) + 0.5, single MUFU
__device__ __forceinline__ float fast_sigmoid_half(float zh) {
    float t;
    asm("tanh.approx.f32 %0, %1;" : "=f"(t) : "f"(zh));
    return fmaf(t, 0.5f, 0.5f);
}
// Streaming (evict-first) 8B store: output is never re-read; keep operands in L2.
__device__ __forceinline__ void stg_cs_f2(float* p, float x, float y) {
    asm volatile("st.global.cs.v2.f32 [%0], {%1, %2};" :: "l"(p), "f"(x), "f"(y) : "memory");
}

// ---------------------------------------------------------------------------
// Kernel 0 (fused): split x -> xp [hi|lo] (8 elems/thread, uint4 stores)
//                   AND pack W -> wp
// ---------------------------------------------------------------------------
#define NX8 (MTOT * D / 8)
#define NW  (D * D)

__global__ __launch_bounds__(256) void split_pack_kernel(const float* __restrict__ X,
                                                         const float* __restrict__ W)
{
    int gi = blockIdx.x * blockDim.x + threadIdx.x;
    if (gi < NX8) {
        const float4* X4 = reinterpret_cast<const float4*>(X);
        float4 v0 = X4[gi * 2];
        float4 v1 = X4[gi * 2 + 1];
        float vv[8] = {v0.x, v0.y, v0.z, v0.w, v1.x, v1.y, v1.z, v1.w};
        uint32_t hp[4], lp[4];
#pragma unroll
        for (int q = 0; q < 4; q++) {
            __nv_bfloat16 h0 = __float2bfloat16(vv[q * 2]);
            __nv_bfloat16 h1 = __float2bfloat16(vv[q * 2 + 1]);
            __nv_bfloat16 l0 = __float2bfloat16(vv[q * 2]     - __bfloat162float(h0));
            __nv_bfloat16 l1 = __float2bfloat16(vv[q * 2 + 1] - __bfloat162float(h1));
            hp[q] = pack_bf2(h0, h1);
            lp[q] = pack_bf2(l0, l1);
        }
        int row = (gi * 8) / D;
        int col = (gi * 8) % D;        // D % 8 == 0
        __nv_bfloat16* base = g_xp + (size_t)row * KU;
        *reinterpret_cast<uint4*>(base + col)       = make_uint4(hp[0], hp[1], hp[2], hp[3]);
        *reinterpret_cast<uint4*>(base + 320 + col) = make_uint4(lp[0], lp[1], lp[2], lp[3]);
    } else {
        int i = gi - NX8;
        if (i >= NW) return;
        int d = i / D, e = i % D;
        float w = W[(size_t)d * D + e];
        __nv_bfloat16 h = __float2bfloat16(w);
        __nv_bfloat16 l = __float2bfloat16(w - __bfloat162float(h));
        __nv_bfloat16* base = g_wp + (size_t)e * KU;
        base[d]       = h;
        base[320 + d] = l;
    }
}

// ---------------------------------------------------------------------------
// Kernel 1: y = x @ W via compensated bf16 mma (NT: A=xp, B=wp).
// CTA 128x64, 8 warps (4m x 2n), warp 32x32. 3-stage pipe, mid-loop issue.
// A-loader specialized on interior row blocks (128 of 129 need no checks).
// Epilogue -> yp [hi | lo].
// ---------------------------------------------------------------------------
#define XW_STAGE ((128 + 64) * 128)              // 24576 B
#define XW_NSTAGE 3
#define XW_NKB 10

__global__ __launch_bounds__(256, 2) void xw_mma(void)
{
    extern __shared__ char smem[];
    const uint32_t sbase = smem_u32(smem);
    const int tid  = threadIdx.x;
    const int wid  = tid >> 5;
    const int lane = tid & 31;

    const int row0 = blockIdx.y * 128;
    const int col0 = blockIdx.x * 64;
    const bool interior = (row0 + 128 <= MTOT);
    const int wm = (wid >> 1) * 32;
    const int wn = (wid & 1) * 32;

    float acc[2][4][4];
#pragma unroll
    for (int mi = 0; mi < 2; mi++)
#pragma unroll
        for (int ni = 0; ni < 4; ni++)
#pragma unroll
            for (int e = 0; e < 4; e++) acc[mi][ni][e] = 0.0f;

    auto load_tiles_t = [&](int kb, bool chk) {
        if (kb >= XW_NKB) return;
        const uint32_t stage = sbase + (uint32_t)(kb % XW_NSTAGE) * XW_STAGE;
        const int koff = kb * 32;
#pragma unroll
        for (int it = tid; it < 1024; it += 256) {
            int r = it >> 3, c = it & 7;
            int scol = koff + (c & 3) * 8 + ((c >> 2) * 320);
            uint32_t dst = stage + sw128((uint32_t)(r * 128 + c * 16));
            int grow = row0 + r;
            if (!chk || grow < MTOT) cp_async16(dst, g_xp + (size_t)grow * KU + scol);
            else *reinterpret_cast<uint4*>(smem + (dst - sbase)) = make_uint4(0, 0, 0, 0);
        }
#pragma unroll
        for (int it = tid; it < 512; it += 256) {
            int r = it >> 3, c = it & 7;
            int scol = koff + (c & 3) * 8 + ((c >> 2) * 320);
            uint32_t dst = stage + 16384 + sw128((uint32_t)(r * 128 + c * 16));
            cp_async16(dst, g_wp + (size_t)(col0 + r) * KU + scol);
        }
    };
    auto load_tiles = [&](int kb) {
        if (interior) load_tiles_t(kb, false);
        else          load_tiles_t(kb, true);
    };

    load_tiles(0); cp_commit();
    load_tiles(1); cp_commit();

    for (int kb = 0; kb < XW_NKB; kb++) {
        cp_wait<1>();
        __syncthreads();

        const uint32_t sA = sbase + (uint32_t)(kb % XW_NSTAGE) * XW_STAGE;
        const uint32_t sB = sA + 16384;

#pragma unroll
        for (int ks = 0; ks < 2; ks++) {
            uint32_t a[2][4], bh[2][4], bl[2][4];
            const int ca = ks * 2 + (lane >> 4);
            const int cb = ks * 2 + ((lane >> 3) & 1);
#pragma unroll
            for (int mi = 0; mi < 2; mi++) {
                int r = wm + mi * 16 + (lane & 7) + ((lane >> 3) & 1) * 8;
                ldmatrix_x4(a[mi], sA + sw128((uint32_t)(r * 128 + ca * 16)));
            }
#pragma unroll
            for (int nj = 0; nj < 2; nj++) {
                int n = wn + nj * 16 + (lane & 7) + (lane >> 4) * 8;
                ldmatrix_x4(bh[nj], sB + sw128((uint32_t)(n * 128 + cb * 16)));
                ldmatrix_x4(bl[nj], sB + sw128((uint32_t)(n * 128 + (cb + 4) * 16)));
            }
#pragma unroll
            for (int nj = 0; nj < 2; nj++)
#pragma unroll
                for (int mi = 0; mi < 2; mi++) {
                    mma16816(acc[mi][nj * 2],     a[mi], bh[nj][0], bh[nj][1]);
                    mma16816(acc[mi][nj * 2 + 1], a[mi], bh[nj][2], bh[nj][3]);
                    mma16816(acc[mi][nj * 2],     a[mi], bl[nj][0], bl[nj][1]);
                    mma16816(acc[mi][nj * 2 + 1], a[mi], bl[nj][2], bl[nj][3]);
                }
#pragma unroll
            for (int mi = 0; mi < 2; mi++) {
                int r = wm + mi * 16 + (lane & 7) + ((lane >> 3) & 1) * 8;
                ldmatrix_x4(a[mi], sA + sw128((uint32_t)(r * 128 + (ca + 4) * 16)));
            }
#pragma unroll
            for (int nj = 0; nj < 2; nj++)
#pragma unroll
                for (int mi = 0; mi < 2; mi++) {
                    mma16816(acc[mi][nj * 2],     a[mi], bh[nj][0], bh[nj][1]);
                    mma16816(acc[mi][nj * 2 + 1], a[mi], bh[nj][2], bh[nj][3]);
                }
            if (ks == 0) { load_tiles(kb + 2); cp_commit(); }
        }
    }

#pragma unroll
    for (int mi = 0; mi < 2; mi++) {
        int r0 = row0 + wm + mi * 16 + (lane >> 2);
#pragma unroll
        for (int ni = 0; ni < 4; ni++) {
            int col = col0 + wn + ni * 8 + (lane & 3) * 2;
#pragma unroll
            for (int h = 0; h < 2; h++) {
                int row = r0 + h * 8;
                if (!interior && row >= MTOT) continue;
                float v0 = acc[mi][ni][h * 2];
                float v1 = acc[mi][ni][h * 2 + 1];
                __nv_bfloat16 h0 = __float2bfloat16(v0);
                __nv_bfloat16 h1 = __float2bfloat16(v1);
                __nv_bfloat16 l0 = __float2bfloat16(v0 - __bfloat162float(h0));
                __nv_bfloat16 l1 = __float2bfloat16(v1 - __bfloat162float(h1));
                __nv_bfloat16* base = g_yp + (size_t)row * KU;
                *reinterpret_cast<uint32_t*>(base + col)       = pack_bf2(h0, h1);
                *reinterpret_cast<uint32_t*>(base + 320 + col) = pack_bf2(l0, l1);
            }
        }
    }
}

// ---------------------------------------------------------------------------
// Kernel 2: out = sigmoid(yp · xp^T + bias).  Unique K=640, 10 kb of 32.
// CTA 128x128, 8 warps (2m x 4n), warp 64x32, 2 CTAs/SM, 3-stage pipe,
// single mid-kb prefetch issue, streaming .cs epilogue stores (R13-exact),
// PLUS per-CTA interior specialization: 16x16 of 17x17 tiles run with zero
// bounds predicates in loads and epilogue.
// ---------------------------------------------------------------------------
#define BL_STAGE ((128 + 128) * 128)             // 32768 B per stage
#define BL_NSTAGE 3
#define BL_NKB 10

__global__ __launch_bounds__(256, 2) void bilinear_mma(const float* __restrict__ bias,
                                                       float* __restrict__ out)
{
    extern __shared__ char smem[];
    const uint32_t sbase = smem_u32(smem);
    const int tid  = threadIdx.x;
    const int wid  = tid >> 5;
    const int lane = tid & 31;

    const int b    = blockIdx.z;
    const int row0 = blockIdx.y * 128;
    const int col0 = blockIdx.x * 128;
    const bool interior = (row0 + 128 <= L) && (col0 + 128 <= L);

    const __nv_bfloat16* Ag = g_yp + (size_t)b * L * KU;
    const __nv_bfloat16* Bg = g_xp + (size_t)b * L * KU;

    const int wm = (wid >> 2) * 64;
    const int wn = (wid & 3) * 32;

    float acc[4][4][4];
#pragma unroll
    for (int mi = 0; mi < 4; mi++)
#pragma unroll
        for (int ni = 0; ni < 4; ni++)
#pragma unroll
            for (int e = 0; e < 4; e++) acc[mi][ni][e] = 0.0f;

    auto load_tiles_t = [&](int kb, bool chk) {
        if (kb >= BL_NKB) return;
        const uint32_t stage = sbase + (uint32_t)(kb % BL_NSTAGE) * BL_STAGE;
        const int koff = kb * 32;
#pragma unroll
        for (int it = tid; it < 1024; it += 256) {
            int r = it >> 3, c = it & 7;
            int scol = koff + (c & 3) * 8 + ((c >> 2) * 320);
            uint32_t dst = stage + sw128((uint32_t)(r * 128 + c * 16));
            int grow = row0 + r;
            if (!chk || grow < L) cp_async16(dst, Ag + (size_t)grow * KU + scol);
            else *reinterpret_cast<uint4*>(smem + (dst - sbase)) = make_uint4(0, 0, 0, 0);
        }
#pragma unroll
        for (int it = tid; it < 1024; it += 256) {
            int r = it >> 3, c = it & 7;
            int scol = koff + (c & 3) * 8 + ((c >> 2) * 320);
            uint32_t dst = stage + 16384 + sw128((uint32_t)(r * 128 + c * 16));
            int grow = col0 + r;
            if (!chk || grow < L) cp_async16(dst, Bg + (size_t)grow * KU + scol);
            else *reinterpret_cast<uint4*>(smem + (dst - sbase)) = make_uint4(0, 0, 0, 0);
        }
    };
    auto load_tiles = [&](int kb) {
        if (interior) load_tiles_t(kb, false);
        else          load_tiles_t(kb, true);
    };

    load_tiles(0); cp_commit();
    load_tiles(1); cp_commit();

    for (int kb = 0; kb < BL_NKB; kb++) {
        cp_wait<1>();
        __syncthreads();

        const uint32_t sA = sbase + (uint32_t)(kb % BL_NSTAGE) * BL_STAGE;
        const uint32_t sB = sA + 16384;

#pragma unroll
        for (int ks = 0; ks < 2; ks++) {
            uint32_t a[4][4], bh[2][4], bl[2][4];
            const int ca = ks * 2 + (lane >> 4);
            const int cb = ks * 2 + ((lane >> 3) & 1);
#pragma unroll
            for (int mi = 0; mi < 4; mi++) {
                int r = wm + mi * 16 + (lane & 7) + ((lane >> 3) & 1) * 8;
                ldmatrix_x4(a[mi], sA + sw128((uint32_t)(r * 128 + ca * 16)));
            }
#pragma unroll
            for (int nj = 0; nj < 2; nj++) {
                int n = wn + nj * 16 + (lane & 7) + (lane >> 4) * 8;
                ldmatrix_x4(bh[nj], sB + sw128((uint32_t)(n * 128 + cb * 16)));
                ldmatrix_x4(bl[nj], sB + sw128((uint32_t)(n * 128 + (cb + 4) * 16)));
            }
#pragma unroll
            for (int nj = 0; nj < 2; nj++)
#pragma unroll
                for (int mi = 0; mi < 4; mi++) {
                    mma16816(acc[mi][nj * 2],     a[mi], bh[nj][0], bh[nj][1]);
                    mma16816(acc[mi][nj * 2 + 1], a[mi], bh[nj][2], bh[nj][3]);
                    mma16816(acc[mi][nj * 2],     a[mi], bl[nj][0], bl[nj][1]);
                    mma16816(acc[mi][nj * 2 + 1], a[mi], bl[nj][2], bl[nj][3]);
                }
#pragma unroll
            for (int mi = 0; mi < 4; mi++) {
                int r = wm + mi * 16 + (lane & 7) + ((lane >> 3) & 1) * 8;
                ldmatrix_x4(a[mi], sA + sw128((uint32_t)(r * 128 + (ca + 4) * 16)));
            }
#pragma unroll
            for (int nj = 0; nj < 2; nj++)
#pragma unroll
                for (int mi = 0; mi < 4; mi++) {
                    mma16816(acc[mi][nj * 2],     a[mi], bh[nj][0], bh[nj][1]);
                    mma16816(acc[mi][nj * 2 + 1], a[mi], bh[nj][2], bh[nj][3]);
                }
            if (ks == 0) { load_tiles(kb + 2); cp_commit(); }
        }
    }

    // Epilogue: sigmoid(z) = 0.5*tanh(0.5*(z+bias)) + 0.5, streaming stores.
    const float hb = 0.5f * bias[0];
    float* obase = out + (size_t)b * L * L;
    if (interior) {
#pragma unroll
        for (int mi = 0; mi < 4; mi++) {
            int r0 = row0 + wm + mi * 16 + (lane >> 2);
#pragma unroll
            for (int ni = 0; ni < 4; ni++) {
                int col = col0 + wn + ni * 8 + (lane & 3) * 2;
#pragma unroll
                for (int h = 0; h < 2; h++) {
                    int row = r0 + h * 8;
                    float zh0 = fmaf(acc[mi][ni][h * 2],     0.5f, hb);
                    float zh1 = fmaf(acc[mi][ni][h * 2 + 1], 0.5f, hb);
                    stg_cs_f2(&obase[(size_t)row * L + col],
                              fast_sigmoid_half(zh0), fast_sigmoid_half(zh1));
                }
            }
        }
    } else {
#pragma unroll
        for (int mi = 0; mi < 4; mi++) {
            int r0 = row0 + wm + mi * 16 + (lane >> 2);
#pragma unroll
            for (int ni = 0; ni < 4; ni++) {
                int col = col0 + wn + ni * 8 + (lane & 3) * 2;
                if (col >= L) continue;
#pragma unroll
                for (int h = 0; h < 2; h++) {
                    int row = r0 + h * 8;
                    if (row >= L) continue;
                    float zh0 = fmaf(acc[mi][ni][h * 2],     0.5f, hb);
                    float zh1 = fmaf(acc[mi][ni][h * 2 + 1], 0.5f, hb);
                    stg_cs_f2(&obase[(size_t)row * L + col],
                              fast_sigmoid_half(zh0), fast_sigmoid_half(zh1));
                }
            }
        }
    }
}

// ---------------------------------------------------------------------------
extern "C" void kernel_launch(void* const* d_in, const int* in_sizes, int n_in,
                              void* d_out, int out_size)
{
    const float* x    = (const float*)d_in[0];   // (8, 2050, 320)
    const float* W    = (const float*)d_in[1];   // (320, 320)
    const float* bias = (const float*)d_in[2];   // (1,)
    float* out = (float*)d_out;                  // (8, 2050, 2050)

    cudaFuncSetAttribute(xw_mma, cudaFuncAttributeMaxDynamicSharedMemorySize,
                         XW_NSTAGE * XW_STAGE);
    cudaFuncSetAttribute(bilinear_mma, cudaFuncAttributeMaxDynamicSharedMemorySize,
                         BL_NSTAGE * BL_STAGE);

    {
        int ntot = NX8 + NW;
        split_pack_kernel<<<(ntot + 255) / 256, 256>>>(x, W);
    }
    {
        dim3 grid(D / 64, (MTOT + 127) / 128);            // (5, 129)
        xw_mma<<<grid, 256, XW_NSTAGE * XW_STAGE>>>();
    }
    {
        dim3 grid((L + 127) / 128, (L + 127) / 128, NB);  // (17,17,8)
        bilinear_mma<<<grid, 256, BL_NSTAGE * BL_STAGE>>>(bias, out);
    }
}

// round 16
// speedup vs baseline: 1.0725x; 1.0001x over previous
#include <cuda_runtime.h>
#include <cuda_bf16.h>
#include <cstdint>

#define NB 8
#define L  2050
#define D  320
#define KU 640              // unique packed K = 2*D  (hi | lo)
#define MTOT (NB * L)

// ---------------------------------------------------------------------------
// Compact packed bf16 operands (unique data only):
//   xp row = [x_hi(320) | x_lo(320)],  yp row = [y_hi(320) | y_lo(320)]
//   wp row e = [Wh(:,e)(320) | Wl(:,e)(320)]
// Compensated product by fragment reuse: acc += ah*bh + ah*bl + al*bh
// ---------------------------------------------------------------------------
__device__ __align__(1024) __nv_bfloat16 g_xp[MTOT * KU];
__device__ __align__(1024) __nv_bfloat16 g_yp[MTOT * KU];
__device__ __align__(1024) __nv_bfloat16 g_wp[D * KU];

__device__ __forceinline__ uint32_t smem_u32(const void* p) {
    uint32_t a;
    asm("{ .reg .u64 t; cvta.to.shared.u64 t, %1; cvt.u32.u64 %0, t; }" : "=r"(a) : "l"(p));
    return a;
}
__device__ __forceinline__ void cp_async16(uint32_t dst, const void* src) {
    asm volatile("cp.async.cg.shared.global [%0], [%1], 16;" :: "r"(dst), "l"(src) : "memory");
}
__device__ __forceinline__ void cp_commit() {
    asm volatile("cp.async.commit_group;" ::: "memory");
}
template <int N>
__device__ __forceinline__ void cp_wait() {
    asm volatile("cp.async.wait_group %0;" :: "n"(N) : "memory");
}
__device__ __forceinline__ void ldmatrix_x4(uint32_t* r, uint32_t addr) {
    asm volatile("ldmatrix.sync.aligned.m8n8.x4.shared.b16 {%0,%1,%2,%3}, [%4];"
                 : "=r"(r[0]), "=r"(r[1]), "=r"(r[2]), "=r"(r[3]) : "r"(addr));
}
__device__ __forceinline__ void mma16816(float* c, const uint32_t* a, uint32_t b0, uint32_t b1) {
    asm volatile("mma.sync.aligned.m16n8k16.row.col.f32.bf16.bf16.f32 "
                 "{%0,%1,%2,%3}, {%4,%5,%6,%7}, {%8,%9}, {%0,%1,%2,%3};"
                 : "+f"(c[0]), "+f"(c[1]), "+f"(c[2]), "+f"(c[3])
                 : "r"(a[0]), "r"(a[1]), "r"(a[2]), "r"(a[3]), "r"(b0), "r"(b1));
}
__device__ __forceinline__ uint32_t sw128(uint32_t off) {
    return off ^ ((off >> 3) & 0x70);
}
__device__ __forceinline__ uint32_t pack_bf2(__nv_bfloat16 a, __nv_bfloat16 b) {
    return (uint32_t)__bfloat16_as_ushort(a) | ((uint32_t)__bfloat16_as_ushort(b) << 16);
}
// sigmoid(z) = 0.5*tanh(0.5*z) + 0.5, single MUFU
__device__ __forceinline__ float fast_sigmoid_half(float zh) {
    float t;
    asm("tanh.approx.f32 %0, %1;" : "=f"(t) : "f"(zh));
    return fmaf(t, 0.5f, 0.5f);
}
// Streaming (evict-first) 8B store: output is never re-read; keep operands in L2.
__device__ __forceinline__ void stg_cs_f2(float* p, float x, float y) {
    asm volatile("st.global.cs.v2.f32 [%0], {%1, %2};" :: "l"(p), "f"(x), "f"(y) : "memory");
}

// ---------------------------------------------------------------------------
// Kernel 0 (fused): split x -> xp [hi|lo] (8 elems/thread, uint4 stores)
//                   AND pack W -> wp
// ---------------------------------------------------------------------------
#define NX8 (MTOT * D / 8)
#define NW  (D * D)

__global__ __launch_bounds__(256) void split_pack_kernel(const float* __restrict__ X,
                                                         const float* __restrict__ W)
{
    int gi = blockIdx.x * blockDim.x + threadIdx.x;
    if (gi < NX8) {
        const float4* X4 = reinterpret_cast<const float4*>(X);
        float4 v0 = X4[gi * 2];
        float4 v1 = X4[gi * 2 + 1];
        float vv[8] = {v0.x, v0.y, v0.z, v0.w, v1.x, v1.y, v1.z, v1.w};
        uint32_t hp[4], lp[4];
#pragma unroll
        for (int q = 0; q < 4; q++) {
            __nv_bfloat16 h0 = __float2bfloat16(vv[q * 2]);
            __nv_bfloat16 h1 = __float2bfloat16(vv[q * 2 + 1]);
            __nv_bfloat16 l0 = __float2bfloat16(vv[q * 2]     - __bfloat162float(h0));
            __nv_bfloat16 l1 = __float2bfloat16(vv[q * 2 + 1] - __bfloat162float(h1));
            hp[q] = pack_bf2(h0, h1);
            lp[q] = pack_bf2(l0, l1);
        }
        int row = (gi * 8) / D;
        int col = (gi * 8) % D;        // D % 8 == 0
        __nv_bfloat16* base = g_xp + (size_t)row * KU;
        *reinterpret_cast<uint4*>(base + col)       = make_uint4(hp[0], hp[1], hp[2], hp[3]);
        *reinterpret_cast<uint4*>(base + 320 + col) = make_uint4(lp[0], lp[1], lp[2], lp[3]);
    } else {
        int i = gi - NX8;
        if (i >= NW) return;
        int d = i / D, e = i % D;
        float w = W[(size_t)d * D + e];
        __nv_bfloat16 h = __float2bfloat16(w);
        __nv_bfloat16 l = __float2bfloat16(w - __bfloat162float(h));
        __nv_bfloat16* base = g_wp + (size_t)e * KU;
        base[d]       = h;
        base[320 + d] = l;
    }
}

// ---------------------------------------------------------------------------
// Kernel 1: y = x @ W via compensated bf16 mma (NT: A=xp, B=wp).
// CTA 128x64, 8 warps (4m x 2n), warp 32x32. 3-stage pipe, mid-loop issue,
// interior specialization, FULLY UNROLLED kb loop (stage idx compile-time).
// Epilogue -> yp [hi | lo].
// ---------------------------------------------------------------------------
#define XW_STAGE ((128 + 64) * 128)              // 24576 B
#define XW_NSTAGE 3
#define XW_NKB 10

__global__ __launch_bounds__(256, 2) void xw_mma(void)
{
    extern __shared__ char smem[];
    const uint32_t sbase = smem_u32(smem);
    const int tid  = threadIdx.x;
    const int wid  = tid >> 5;
    const int lane = tid & 31;

    const int row0 = blockIdx.y * 128;
    const int col0 = blockIdx.x * 64;
    const bool interior = (row0 + 128 <= MTOT);
    const int wm = (wid >> 1) * 32;
    const int wn = (wid & 1) * 32;

    float acc[2][4][4];
#pragma unroll
    for (int mi = 0; mi < 2; mi++)
#pragma unroll
        for (int ni = 0; ni < 4; ni++)
#pragma unroll
            for (int e = 0; e < 4; e++) acc[mi][ni][e] = 0.0f;

    auto load_tiles_t = [&](int kb, bool chk) {
        if (kb >= XW_NKB) return;
        const uint32_t stage = sbase + (uint32_t)(kb % XW_NSTAGE) * XW_STAGE;
        const int koff = kb * 32;
#pragma unroll
        for (int it = tid; it < 1024; it += 256) {
            int r = it >> 3, c = it & 7;
            int scol = koff + (c & 3) * 8 + ((c >> 2) * 320);
            uint32_t dst = stage + sw128((uint32_t)(r * 128 + c * 16));
            int grow = row0 + r;
            if (!chk || grow < MTOT) cp_async16(dst, g_xp + (size_t)grow * KU + scol);
            else *reinterpret_cast<uint4*>(smem + (dst - sbase)) = make_uint4(0, 0, 0, 0);
        }
#pragma unroll
        for (int it = tid; it < 512; it += 256) {
            int r = it >> 3, c = it & 7;
            int scol = koff + (c & 3) * 8 + ((c >> 2) * 320);
            uint32_t dst = stage + 16384 + sw128((uint32_t)(r * 128 + c * 16));
            cp_async16(dst, g_wp + (size_t)(col0 + r) * KU + scol);
        }
    };
    auto load_tiles = [&](int kb) {
        if (interior) load_tiles_t(kb, false);
        else          load_tiles_t(kb, true);
    };

    load_tiles(0); cp_commit();
    load_tiles(1); cp_commit();

#pragma unroll
    for (int kb = 0; kb < XW_NKB; kb++) {
        cp_wait<1>();
        __syncthreads();

        const uint32_t sA = sbase + (uint32_t)(kb % XW_NSTAGE) * XW_STAGE;
        const uint32_t sB = sA + 16384;

#pragma unroll
        for (int ks = 0; ks < 2; ks++) {
            uint32_t a[2][4], bh[2][4], bl[2][4];
            const int ca = ks * 2 + (lane >> 4);
            const int cb = ks * 2 + ((lane >> 3) & 1);
#pragma unroll
            for (int mi = 0; mi < 2; mi++) {
                int r = wm + mi * 16 + (lane & 7) + ((lane >> 3) & 1) * 8;
                ldmatrix_x4(a[mi], sA + sw128((uint32_t)(r * 128 + ca * 16)));
            }
#pragma unroll
            for (int nj = 0; nj < 2; nj++) {
                int n = wn + nj * 16 + (lane & 7) + (lane >> 4) * 8;
                ldmatrix_x4(bh[nj], sB + sw128((uint32_t)(n * 128 + cb * 16)));
                ldmatrix_x4(bl[nj], sB + sw128((uint32_t)(n * 128 + (cb + 4) * 16)));
            }
#pragma unroll
            for (int nj = 0; nj < 2; nj++)
#pragma unroll
                for (int mi = 0; mi < 2; mi++) {
                    mma16816(acc[mi][nj * 2],     a[mi], bh[nj][0], bh[nj][1]);
                    mma16816(acc[mi][nj * 2 + 1], a[mi], bh[nj][2], bh[nj][3]);
                    mma16816(acc[mi][nj * 2],     a[mi], bl[nj][0], bl[nj][1]);
                    mma16816(acc[mi][nj * 2 + 1], a[mi], bl[nj][2], bl[nj][3]);
                }
#pragma unroll
            for (int mi = 0; mi < 2; mi++) {
                int r = wm + mi * 16 + (lane & 7) + ((lane >> 3) & 1) * 8;
                ldmatrix_x4(a[mi], sA + sw128((uint32_t)(r * 128 + (ca + 4) * 16)));
            }
#pragma unroll
            for (int nj = 0; nj < 2; nj++)
#pragma unroll
                for (int mi = 0; mi < 2; mi++) {
                    mma16816(acc[mi][nj * 2],     a[mi], bh[nj][0], bh[nj][1]);
                    mma16816(acc[mi][nj * 2 + 1], a[mi], bh[nj][2], bh[nj][3]);
                }
            if (ks == 0) { load_tiles(kb + 2); cp_commit(); }
        }
    }

#pragma unroll
    for (int mi = 0; mi < 2; mi++) {
        int r0 = row0 + wm + mi * 16 + (lane >> 2);
#pragma unroll
        for (int ni = 0; ni < 4; ni++) {
            int col = col0 + wn + ni * 8 + (lane & 3) * 2;
#pragma unroll
            for (int h = 0; h < 2; h++) {
                int row = r0 + h * 8;
                if (!interior && row >= MTOT) continue;
                float v0 = acc[mi][ni][h * 2];
                float v1 = acc[mi][ni][h * 2 + 1];
                __nv_bfloat16 h0 = __float2bfloat16(v0);
                __nv_bfloat16 h1 = __float2bfloat16(v1);
                __nv_bfloat16 l0 = __float2bfloat16(v0 - __bfloat162float(h0));
                __nv_bfloat16 l1 = __float2bfloat16(v1 - __bfloat162float(h1));
                __nv_bfloat16* base = g_yp + (size_t)row * KU;
                *reinterpret_cast<uint32_t*>(base + col)       = pack_bf2(h0, h1);
                *reinterpret_cast<uint32_t*>(base + 320 + col) = pack_bf2(l0, l1);
            }
        }
    }
}

// ---------------------------------------------------------------------------
// Kernel 2: out = sigmoid(yp · xp^T + bias).  Unique K=640, 10 kb of 32.
// CTA 128x128, 8 warps (2m x 4n), warp 64x32, 2 CTAs/SM, 3-stage pipe,
// single mid-kb prefetch issue, streaming .cs epilogue stores, interior
// specialization (R14-exact), PLUS fully unrolled kb loop so the stage
// index kb%3 and all smem addresses are compile-time constants.
// ---------------------------------------------------------------------------
#define BL_STAGE ((128 + 128) * 128)             // 32768 B per stage
#define BL_NSTAGE 3
#define BL_NKB 10

__global__ __launch_bounds__(256, 2) void bilinear_mma(const float* __restrict__ bias,
                                                       float* __restrict__ out)
{
    extern __shared__ char smem[];
    const uint32_t sbase = smem_u32(smem);
    const int tid  = threadIdx.x;
    const int wid  = tid >> 5;
    const int lane = tid & 31;

    const int b    = blockIdx.z;
    const int row0 = blockIdx.y * 128;
    const int col0 = blockIdx.x * 128;
    const bool interior = (row0 + 128 <= L) && (col0 + 128 <= L);

    const __nv_bfloat16* Ag = g_yp + (size_t)b * L * KU;
    const __nv_bfloat16* Bg = g_xp + (size_t)b * L * KU;

    const int wm = (wid >> 2) * 64;
    const int wn = (wid & 3) * 32;

    float acc[4][4][4];
#pragma unroll
    for (int mi = 0; mi < 4; mi++)
#pragma unroll
        for (int ni = 0; ni < 4; ni++)
#pragma unroll
            for (int e = 0; e < 4; e++) acc[mi][ni][e] = 0.0f;

    auto load_tiles_t = [&](int kb, bool chk) {
        if (kb >= BL_NKB) return;
        const uint32_t stage = sbase + (uint32_t)(kb % BL_NSTAGE) * BL_STAGE;
        const int koff = kb * 32;
#pragma unroll
        for (int it = tid; it < 1024; it += 256) {
            int r = it >> 3, c = it & 7;
            int scol = koff + (c & 3) * 8 + ((c >> 2) * 320);
            uint32_t dst = stage + sw128((uint32_t)(r * 128 + c * 16));
            int grow = row0 + r;
            if (!chk || grow < L) cp_async16(dst, Ag + (size_t)grow * KU + scol);
            else *reinterpret_cast<uint4*>(smem + (dst - sbase)) = make_uint4(0, 0, 0, 0);
        }
#pragma unroll
        for (int it = tid; it < 1024; it += 256) {
            int r = it >> 3, c = it & 7;
            int scol = koff + (c & 3) * 8 + ((c >> 2) * 320);
            uint32_t dst = stage + 16384 + sw128((uint32_t)(r * 128 + c * 16));
            int grow = col0 + r;
            if (!chk || grow < L) cp_async16(dst, Bg + (size_t)grow * KU + scol);
            else *reinterpret_cast<uint4*>(smem + (dst - sbase)) = make_uint4(0, 0, 0, 0);
        }
    };
    auto load_tiles = [&](int kb) {
        if (interior) load_tiles_t(kb, false);
        else          load_tiles_t(kb, true);
    };

    load_tiles(0); cp_commit();
    load_tiles(1); cp_commit();

#pragma unroll
    for (int kb = 0; kb < BL_NKB; kb++) {
        cp_wait<1>();
        __syncthreads();

        const uint32_t sA = sbase + (uint32_t)(kb % BL_NSTAGE) * BL_STAGE;
        const uint32_t sB = sA + 16384;

#pragma unroll
        for (int ks = 0; ks < 2; ks++) {
            uint32_t a[4][4], bh[2][4], bl[2][4];
            const int ca = ks * 2 + (lane >> 4);
            const int cb = ks * 2 + ((lane >> 3) & 1);
#pragma unroll
            for (int mi = 0; mi < 4; mi++) {
                int r = wm + mi * 16 + (lane & 7) + ((lane >> 3) & 1) * 8;
                ldmatrix_x4(a[mi], sA + sw128((uint32_t)(r * 128 + ca * 16)));
            }
#pragma unroll
            for (int nj = 0; nj < 2; nj++) {
                int n = wn + nj * 16 + (lane & 7) + (lane >> 4) * 8;
                ldmatrix_x4(bh[nj], sB + sw128((uint32_t)(n * 128 + cb * 16)));
                ldmatrix_x4(bl[nj], sB + sw128((uint32_t)(n * 128 + (cb + 4) * 16)));
            }
#pragma unroll
            for (int nj = 0; nj < 2; nj++)
#pragma unroll
                for (int mi = 0; mi < 4; mi++) {
                    mma16816(acc[mi][nj * 2],     a[mi], bh[nj][0], bh[nj][1]);
                    mma16816(acc[mi][nj * 2 + 1], a[mi], bh[nj][2], bh[nj][3]);
                    mma16816(acc[mi][nj * 2],     a[mi], bl[nj][0], bl[nj][1]);
                    mma16816(acc[mi][nj * 2 + 1], a[mi], bl[nj][2], bl[nj][3]);
                }
#pragma unroll
            for (int mi = 0; mi < 4; mi++) {
                int r = wm + mi * 16 + (lane & 7) + ((lane >> 3) & 1) * 8;
                ldmatrix_x4(a[mi], sA + sw128((uint32_t)(r * 128 + (ca + 4) * 16)));
            }
#pragma unroll
            for (int nj = 0; nj < 2; nj++)
#pragma unroll
                for (int mi = 0; mi < 4; mi++) {
                    mma16816(acc[mi][nj * 2],     a[mi], bh[nj][0], bh[nj][1]);
                    mma16816(acc[mi][nj * 2 + 1], a[mi], bh[nj][2], bh[nj][3]);
                }
            if (ks == 0) { load_tiles(kb + 2); cp_commit(); }
        }
    }

    // Epilogue: sigmoid(z) = 0.5*tanh(0.5*(z+bias)) + 0.5, streaming stores.
    const float hb = 0.5f * bias[0];
    float* obase = out + (size_t)b * L * L;
    if (interior) {
#pragma unroll
        for (int mi = 0; mi < 4; mi++) {
            int r0 = row0 + wm + mi * 16 + (lane >> 2);
#pragma unroll
            for (int ni = 0; ni < 4; ni++) {
                int col = col0 + wn + ni * 8 + (lane & 3) * 2;
#pragma unroll
                for (int h = 0; h < 2; h++) {
                    int row = r0 + h * 8;
                    float zh0 = fmaf(acc[mi][ni][h * 2],     0.5f, hb);
                    float zh1 = fmaf(acc[mi][ni][h * 2 + 1], 0.5f, hb);
                    stg_cs_f2(&obase[(size_t)row * L + col],
                              fast_sigmoid_half(zh0), fast_sigmoid_half(zh1));
                }
            }
        }
    } else {
#pragma unroll
        for (int mi = 0; mi < 4; mi++) {
            int r0 = row0 + wm + mi * 16 + (lane >> 2);
#pragma unroll
            for (int ni = 0; ni < 4; ni++) {
                int col = col0 + wn + ni * 8 + (lane & 3) * 2;
                if (col >= L) continue;
#pragma unroll
                for (int h = 0; h < 2; h++) {
                    int row = r0 + h * 8;
                    if (row >= L) continue;
                    float zh0 = fmaf(acc[mi][ni][h * 2],     0.5f, hb);
                    float zh1 = fmaf(acc[mi][ni][h * 2 + 1], 0.5f, hb);
                    stg_cs_f2(&obase[(size_t)row * L + col],
                              fast_sigmoid_half(zh0), fast_sigmoid_half(zh1));
                }
            }
        }
    }
}

// ---------------------------------------------------------------------------
extern "C" void kernel_launch(void* const* d_in, const int* in_sizes, int n_in,
                              void* d_out, int out_size)
{
    const float* x    = (const float*)d_in[0];   // (8, 2050, 320)
    const float* W    = (const float*)d_in[1];   // (320, 320)
    const float* bias = (const float*)d_in[2];   // (1,)
    float* out = (float*)d_out;                  // (8, 2050, 2050)

    cudaFuncSetAttribute(xw_mma, cudaFuncAttributeMaxDynamicSharedMemorySize,
                         XW_NSTAGE * XW_STAGE);
    cudaFuncSetAttribute(bilinear_mma, cudaFuncAttributeMaxDynamicSharedMemorySize,
                         BL_NSTAGE * BL_STAGE);

    {
        int ntot = NX8 + NW;
        split_pack_kernel<<<(ntot + 255) / 256, 256>>>(x, W);
    }
    {
        dim3 grid(D / 64, (MTOT + 127) / 128);            // (5, 129)
        xw_mma<<<grid, 256, XW_NSTAGE * XW_STAGE>>>();
    }
    {
        dim3 grid((L + 127) / 128, (L + 127) / 128, NB);  // (17,17,8)
        bilinear_mma<<<grid, 256, BL_NSTAGE * BL_STAGE>>>(bias, out);
    }
}